// round 12
// baseline (speedup 1.0000x reference)
#include <cuda_runtime.h>
#include <cuda_bf16.h>
#include <cooperative_groups.h>
#include <cstdint>
#include <cstddef>

namespace cg = cooperative_groups;

// Problem constants (from reference: B=2048, IN=784, H=128, OUT=10, T=100)
#define IN_DIM   784
#define H_DIM    128
#define HH        64      // hidden columns per CTA (cluster of 2 splits H)
#define OUT_DIM   10
#define BETA_F   0.9f
#define ROWS_PER_CLUSTER 32
#define NWARP     16
#define NTHREADS 512
#define NJ        25      // ceil(784/32)
#define TAIL_LANES (IN_DIM - 32*(NJ-1))   // 16

// SMEM: W1 half [784][64] fp32 (200704 B) + W2 [128][10] (5120 B) + spike buf (512 B)
#define SMEM_BYTES ((IN_DIM*HH + H_DIM*OUT_DIM) * sizeof(float) + 2*ROWS_PER_CLUSTER*2*sizeof(unsigned))

__global__ void __launch_bounds__(NTHREADS, 1)
snn_cluster_kernel(const float* __restrict__ x,
                   const float* __restrict__ noise,
                   const float* __restrict__ W1,
                   const float* __restrict__ b1,
                   const float* __restrict__ W2,
                   const float* __restrict__ b2,
                   float* __restrict__ out,
                   int B, int T)
{
    extern __shared__ float smem[];
    float*    W1s = smem;                                  // [784][64], col c = global h (rank*64 + c)
    float*    W2s = smem + IN_DIM * HH;                    // [128][10]
    unsigned* spb = (unsigned*)(W2s + H_DIM * OUT_DIM);    // [2 parity][32 rows][2 words]

    cg::cluster_group cluster = cg::this_cluster();
    const int rank = (int)cluster.block_rank();            // 0 or 1
    const unsigned* rspb =
        (const unsigned*)cluster.map_shared_rank((void*)spb, rank ^ 1);

    const int tid  = threadIdx.x;
    const int wid  = tid >> 5;
    const int lane = tid & 31;
    const int cid  = blockIdx.x >> 1;

    // ---- Stage W1 half + W2 into shared (W1 read from HBM once per CTA) ----
    for (int idx = tid; idx < IN_DIM * HH; idx += NTHREADS) {
        int i = idx >> 6;         // input row
        int c = idx & 63;         // local hidden col
        W1s[idx] = W1[i * H_DIM + rank * HH + c];
    }
    for (int idx = tid; idx < H_DIM * OUT_DIM; idx += NTHREADS)
        W2s[idx] = W2[idx];
    __syncthreads();

    const float b1c0 = b1[rank * HH + 2 * lane];
    const float b1c1 = b1[rank * HH + 2 * lane + 1];
    const float b2v  = (lane < OUT_DIM) ? b2[lane] : 0.0f;

    const int row0 = cid * ROWS_PER_CLUSTER + wid;   // warp's first batch row
    const int row1 = row0 + NWARP;                   // warp's second batch row
    const bool v0 = (row0 < B);
    const bool v1 = (row1 < B);

    // ---- Poisson-encoding probabilities, kept in registers (fp32-exact vs ref) ----
    float pr0[NJ], pr1[NJ];
#pragma unroll
    for (int j = 0; j < NJ; j++) {
        int i = j * 32 + lane;
        float xv0 = (v0 && i < IN_DIM) ? x[(size_t)row0 * IN_DIM + i] : -1.0f;
        float xv1 = (v1 && i < IN_DIM) ? x[(size_t)row1 * IN_DIM + i] : -1.0f;
        pr0[j] = fminf(fmaxf(__fmul_rn(xv0, 0.1f), 0.0f), 1.0f);
        pr1[j] = fminf(fmaxf(__fmul_rn(xv1, 0.1f), 0.0f), 1.0f);
    }

    // Membrane state in registers. Lane covers local h = 2*lane and 2*lane+1.
    float mA0 = 0.0f, mA1 = 0.0f;     // row0, layer-1 half
    float mB0 = 0.0f, mB1 = 0.0f;     // row1, layer-1 half
    float mem2a = 0.0f, mem2b = 0.0f; // layer-2 (rank 0, lanes 0..9 only)
    float cnta = 0.0f, cntb = 0.0f;

    // per-row layer-1 step: spike gen + sparse W1 accumulate + LIF update + ballot
    auto layer1_row = [&](const float (&pr)[NJ], float& m0, float& m1,
                          int row, int rl, int par, int t) {
        const float* np = noise + ((size_t)t * B + row) * IN_DIM;
        // Batch the 25 noise loads first (MLP to hide DRAM latency)
        float nv[NJ];
#pragma unroll
        for (int j = 0; j < NJ; j++) {
            if (j < NJ - 1) nv[j] = np[j * 32 + lane];
            else            nv[j] = (lane < TAIL_LANES) ? np[j * 32 + lane] : 0.0f;
        }
        float a0 = 0.0f, a1 = 0.0f;
#pragma unroll
        for (int j = 0; j < NJ; j++) {
            unsigned m = __ballot_sync(0xffffffffu, nv[j] < pr[j]);
            const float* base = W1s + (j * 32 << 6) + (lane << 1);
            while (m) {
                int bb = __ffs(m) - 1; m &= (m - 1);
                float2 w = *(const float2*)(base + (bb << 6));
                a0 = __fadd_rn(a0, w.x);
                a1 = __fadd_rn(a1, w.y);
            }
        }
        // mem = (beta*mem + dot) + b1, each op rounded (matches reference expr order)
        m0 = __fadd_rn(__fadd_rn(__fmul_rn(BETA_F, m0), a0), b1c0);
        m1 = __fadd_rn(__fadd_rn(__fmul_rn(BETA_F, m1), a1), b1c1);
        bool s0 = (m0 >= 1.0f);
        bool s1 = (m1 >= 1.0f);
        if (s0) m0 = 0.0f;
        if (s1) m1 = 0.0f;
        unsigned e = __ballot_sync(0xffffffffu, s0);  // bit l -> local h = 2l
        unsigned o = __ballot_sync(0xffffffffu, s1);  // bit l -> local h = 2l+1
        if (lane == 0) {
            spb[(par * ROWS_PER_CLUSTER + rl) * 2 + 0] = e;
            spb[(par * ROWS_PER_CLUSTER + rl) * 2 + 1] = o;
        }
    };

    // layer-2 step (rank 0 only, lanes 0..9): gather sp1 halves, LIF, count
    auto layer2_row = [&](float& m2, float& cnt, int rl, int par) {
        unsigned e0 = spb [(par * ROWS_PER_CLUSTER + rl) * 2 + 0];
        unsigned o0 = spb [(par * ROWS_PER_CLUSTER + rl) * 2 + 1];
        unsigned e1 = rspb[(par * ROWS_PER_CLUSTER + rl) * 2 + 0];
        unsigned o1 = rspb[(par * ROWS_PER_CLUSTER + rl) * 2 + 1];
        float s2 = 0.0f;
        unsigned m;
        m = e0; while (m) { int h =      2*(__ffs(m)-1);     m &= m-1; s2 = __fadd_rn(s2, W2s[h*OUT_DIM + lane]); }
        m = o0; while (m) { int h =      2*(__ffs(m)-1) + 1; m &= m-1; s2 = __fadd_rn(s2, W2s[h*OUT_DIM + lane]); }
        m = e1; while (m) { int h = 64 + 2*(__ffs(m)-1);     m &= m-1; s2 = __fadd_rn(s2, W2s[h*OUT_DIM + lane]); }
        m = o1; while (m) { int h = 64 + 2*(__ffs(m)-1) + 1; m &= m-1; s2 = __fadd_rn(s2, W2s[h*OUT_DIM + lane]); }
        m2 = __fadd_rn(__fadd_rn(__fmul_rn(BETA_F, m2), s2), b2v);
        if (m2 >= 1.0f) { cnt = __fadd_rn(cnt, 1.0f); m2 = 0.0f; }
    };

    for (int t = 0; t < T; t++) {
        const int par = t & 1;
        if (v0) layer1_row(pr0, mA0, mA1, row0, wid,         par, t);
        if (v1) layer1_row(pr1, mB0, mB1, row1, wid + NWARP, par, t);

        cluster.sync();   // publish sp1 halves across the pair (double-buffered)

        if (rank == 0 && lane < OUT_DIM) {
            if (v0) layer2_row(mem2a, cnta, wid,         par);
            if (v1) layer2_row(mem2b, cntb, wid + NWARP, par);
        }
    }

    if (rank == 0 && lane < OUT_DIM) {
        if (v0) out[(size_t)row0 * OUT_DIM + lane] = cnta;
        if (v1) out[(size_t)row1 * OUT_DIM + lane] = cntb;
    }

    // CRITICAL: no CTA may exit while its peer can still read this CTA's SMEM
    // via DSMEM (rank 0 reads rspb after the last loop sync). This trailing
    // cluster barrier was missing and caused the unspecified launch failure.
    cluster.sync();
}

extern "C" void kernel_launch(void* const* d_in, const int* in_sizes, int n_in,
                              void* d_out, int out_size) {
    const float* x     = (const float*)d_in[0];
    const float* noise = (const float*)d_in[1];
    const float* W1    = (const float*)d_in[2];
    const float* b1    = (const float*)d_in[3];
    const float* W2    = (const float*)d_in[4];
    const float* b2    = (const float*)d_in[5];
    float* out = (float*)d_out;

    const int B = in_sizes[0] / IN_DIM;                                    // 2048
    const int T = (int)((long long)in_sizes[1] / ((long long)B * IN_DIM)); // 100

    const int numClusters = (B + ROWS_PER_CLUSTER - 1) / ROWS_PER_CLUSTER; // 64

    cudaFuncSetAttribute(snn_cluster_kernel,
                         cudaFuncAttributeMaxDynamicSharedMemorySize,
                         (int)SMEM_BYTES);

    cudaLaunchConfig_t cfg = {};
    cfg.gridDim  = dim3(2 * numClusters, 1, 1);  // 128 CTAs = 64 clusters, single wave
    cfg.blockDim = dim3(NTHREADS, 1, 1);
    cfg.dynamicSmemBytes = SMEM_BYTES;
    cfg.stream = 0;

    cudaLaunchAttribute attrs[1];
    attrs[0].id = cudaLaunchAttributeClusterDimension;
    attrs[0].val.clusterDim.x = 2;
    attrs[0].val.clusterDim.y = 1;
    attrs[0].val.clusterDim.z = 1;
    cfg.attrs = attrs;
    cfg.numAttrs = 1;

    cudaLaunchKernelEx(&cfg, snn_cluster_kernel, x, noise, W1, b1, W2, b2, out, B, T);
}